// round 1
// baseline (speedup 1.0000x reference)
#include <cuda_runtime.h>
#include <cuda_bf16.h>

#define N_NODES 50000
#define N_EDGES 500000
#define H 128
#define G_GRAPHS 100
#define NPG 500
#define NPROT 400
#define PN 35
#define LN 11
#define NLAYERS 4
#define EPS 1e-5f
#define NE_TILE 64

// ---------------- scratch (device globals; no allocations allowed) ----------------
__device__ float g_h[N_NODES * H];
__device__ float g_P1[N_NODES * H];
__device__ float g_P2[N_NODES * H];
__device__ float g_agg[N_NODES * H];
__device__ float g_U[N_NODES * H];
__device__ float g_pos[N_NODES * 3];
__device__ float g_posdelta[N_NODES * 3];
__device__ float g_deg[N_NODES];
__device__ float g_bnstats[2 * H];
__device__ float g_gfeat[G_GRAPHS * 2 * H];

__device__ __forceinline__ float silu_f(float x) {
    return x / (1.f + __expf(-x));
}

// ---------------- embed: h0 = proj(x), copy pos, zero deg/bnstats ----------------
__global__ void k_embed(const float* __restrict__ x, const float* __restrict__ pos_in,
                        const float* __restrict__ Wp, const float* __restrict__ bp,
                        const float* __restrict__ Wl, const float* __restrict__ bl) {
    __shared__ float xs[PN];
    const int i = blockIdx.x;
    const int t = threadIdx.x;
    if (t < PN) xs[t] = x[i * PN + t];
    if (t == 0) g_deg[i] = 0.f;
    if (t < 3) g_pos[i * 3 + t] = pos_in[i * 3 + t];
    if (i == 0 && t < H) { g_bnstats[t] = 0.f; g_bnstats[H + t] = 0.f; }
    __syncthreads();
    const bool isp = (i % NPG) < NPROT;
    const float* W = isp ? Wp : Wl;
    const float* b = isp ? bp : bl;
    const int nk = isp ? PN : LN;
    float acc = b[t];
    for (int k = 0; k < nk; k++) acc += xs[k] * W[k * H + t];
    g_h[i * H + t] = acc;
}

// ---------------- batchnorm stats ----------------
__global__ void k_bnstats() {
    const int j = threadIdx.x;
    float s = 0.f, s2 = 0.f;
    for (int i = blockIdx.x; i < N_NODES; i += gridDim.x) {
        float v = g_h[i * H + j];
        s += v; s2 += v * v;
    }
    atomicAdd(&g_bnstats[j], s);
    atomicAdd(&g_bnstats[H + j], s2);
}

__global__ void k_bnapply(const float* __restrict__ gamma, const float* __restrict__ beta) {
    const int idx = blockIdx.x * blockDim.x + threadIdx.x;
    if (idx >= N_NODES * H) return;
    const int j = idx & (H - 1);
    const float inv_n = 1.f / (float)N_NODES;
    float mu = g_bnstats[j] * inv_n;
    float var = g_bnstats[H + j] * inv_n - mu * mu;
    g_h[idx] = (g_h[idx] - mu) * rsqrtf(var + EPS) * gamma[j] + beta[j];
}

// ---------------- degree ----------------
__global__ void k_deg(const int* __restrict__ ei) {
    const int e = blockIdx.x * blockDim.x + threadIdx.x;
    if (e < N_EDGES) atomicAdd(&g_deg[ei[e]], 1.0f);
}

// ---------------- per-layer node projection: P1 = h@W1a + b1, P2 = h@W1b ----------------
// also zeroes agg and posdelta for this layer.
__global__ __launch_bounds__(512, 1) void k_proj(const float* __restrict__ w,
                                                 const float* __restrict__ b1) {
    extern __shared__ float sm[];
    float* w_s = sm;            // [128][256]  (col jj<128 -> W1a, jj>=128 -> W1b)
    float* a_s = sm + 32768;    // [64][128]
    const int t = threadIdx.x;
    const int n0 = blockIdx.x * 64;

    for (int i = t; i < 32768; i += 512) {
        int k = i >> 8, jj = i & 255;
        int srcrow = (jj < 128) ? k : (128 + k);
        w_s[i] = w[srcrow * H + (jj & 127)];
    }
    for (int i = t; i < 8192; i += 512) {
        int n = i >> 7, k = i & 127;
        int gi = n0 + n;
        a_s[i] = (gi < N_NODES) ? g_h[gi * H + k] : 0.f;
    }
    // zero agg / posdelta for this node range
    for (int i = t; i < 64 * H; i += 512) {
        int gi = n0 + (i >> 7);
        if (gi < N_NODES) g_agg[gi * H + (i & 127)] = 0.f;
    }
    if (t < 192) {
        int gi = n0 + t / 3;
        if (gi < N_NODES) g_posdelta[gi * 3 + t % 3] = 0.f;
    }
    __syncthreads();

    const int jj = t & 255;
    const int eh = t >> 8;      // 0..1, 32 nodes each
    float acc[32];
#pragma unroll
    for (int n = 0; n < 32; n++) acc[n] = 0.f;

    for (int kk = 0; kk < 128; kk += 4) {
        float w4[4];
#pragma unroll
        for (int i = 0; i < 4; i++) w4[i] = w_s[(kk + i) * 256 + jj];
#pragma unroll
        for (int n = 0; n < 32; n++) {
            float4 a = *(const float4*)&a_s[(eh * 32 + n) * H + kk];
            acc[n] += a.x * w4[0];
            acc[n] += a.y * w4[1];
            acc[n] += a.z * w4[2];
            acc[n] += a.w * w4[3];
        }
    }
    const int j = jj & 127;
    const int p = jj >> 7;
    const float bias = p ? 0.f : b1[j];
    float* outp = p ? g_P2 : g_P1;
#pragma unroll
    for (int n = 0; n < 32; n++) {
        int gi = n0 + eh * 32 + n;
        if (gi < N_NODES) outp[gi * H + j] = acc[n] + bias;
    }
}

// ---------------- fused edge kernel ----------------
// hidden = silu(P1[row]+P2[col]+d2*wd2+ea@Wea)   (b1 folded in P1)
// m = silu(hid @ W2 + b2); w = silu(m@C1+cb1) @ C2
// scatter: agg[row] += m;  posdelta[row] += rel*w
__global__ __launch_bounds__(512, 1) void k_edge(
    const int* __restrict__ ei, const float* __restrict__ eattr,
    const float* __restrict__ w2, const float* __restrict__ b2,
    const float* __restrict__ cw1, const float* __restrict__ cb1,
    const float* __restrict__ cw2, const float* __restrict__ ew1) {
    extern __shared__ float sm[];
    float* w2_s  = sm;                // 16384
    float* c1_s  = w2_s + 16384;      // 16384
    float* b2_s  = c1_s + 16384;      // 128
    float* cb1_s = b2_s + 128;        // 128
    float* c2_s  = cb1_s + 128;       // 128
    float* wd2_s = c2_s + 128;        // 128
    float* wea_s = wd2_s + 128;       // 512
    float* hid_s = wea_s + 512;       // 64*128
    float* m_s   = hid_s + 8192;      // 64*128
    float* d2_s  = m_s + 8192;        // 64
    float* rel_s = d2_s + 64;         // 192
    float* ea_s  = rel_s + 192;       // 256
    float* wsum_s = ea_s + 256;       // 64
    float* wred  = wsum_s + 64;       // 128
    int* row_s = (int*)(wred + 128);  // 64
    int* col_s = row_s + 64;          // 64

    const int t = threadIdx.x;
    for (int i = t; i < 16384; i += 512) { w2_s[i] = w2[i]; c1_s[i] = cw1[i]; }
    if (t < 128) {
        b2_s[t] = b2[t]; cb1_s[t] = cb1[t]; c2_s[t] = cw2[t];
        wd2_s[t] = ew1[256 * H + t];
    }
    if (t < 512) wea_s[t] = ew1[257 * H + t];
    __syncthreads();

    const int jp = t & 63;
    const int j0 = jp * 2;
    const int eh = t >> 6;  // 0..7, 8 edges each
    const int ntiles = (N_EDGES + NE_TILE - 1) / NE_TILE;

    for (int tile = blockIdx.x; tile < ntiles; tile += gridDim.x) {
        const int e0 = tile * NE_TILE;
        if (t < NE_TILE) {
            int e = e0 + t;
            int r = 0, c = 0;
            float4 a = make_float4(0.f, 0.f, 0.f, 0.f);
            if (e < N_EDGES) {
                r = ei[e]; c = ei[N_EDGES + e];
                a = *(const float4*)&eattr[e * 4];
            }
            row_s[t] = r; col_s[t] = c;
            float rx = g_pos[r * 3 + 0] - g_pos[c * 3 + 0];
            float ry = g_pos[r * 3 + 1] - g_pos[c * 3 + 1];
            float rz = g_pos[r * 3 + 2] - g_pos[c * 3 + 2];
            rel_s[t * 3 + 0] = rx; rel_s[t * 3 + 1] = ry; rel_s[t * 3 + 2] = rz;
            d2_s[t] = rx * rx + ry * ry + rz * rz;
            ea_s[t * 4 + 0] = a.x; ea_s[t * 4 + 1] = a.y;
            ea_s[t * 4 + 2] = a.z; ea_s[t * 4 + 3] = a.w;
        }
        __syncthreads();

        // Phase A: hidden
#pragma unroll
        for (int rep = 0; rep < 16; rep++) {
            int idx = t + rep * 512;
            int e = idx >> 7, j = idx & 127;
            int r = row_s[e], c = col_s[e];
            float v = g_P1[r * H + j] + g_P2[c * H + j] + d2_s[e] * wd2_s[j];
#pragma unroll
            for (int a2 = 0; a2 < 4; a2++) v += ea_s[e * 4 + a2] * wea_s[a2 * H + j];
            hid_s[e * H + j] = silu_f(v);
        }
        __syncthreads();

        // Phase B: m = silu(hid @ W2 + b2)
        {
            float acc[8][2];
#pragma unroll
            for (int e = 0; e < 8; e++) { acc[e][0] = 0.f; acc[e][1] = 0.f; }
            for (int kk = 0; kk < 128; kk += 4) {
                float2 w01[4];
#pragma unroll
                for (int i = 0; i < 4; i++) w01[i] = *(const float2*)&w2_s[(kk + i) * H + j0];
#pragma unroll
                for (int e = 0; e < 8; e++) {
                    float4 h4 = *(const float4*)&hid_s[(eh * 8 + e) * H + kk];
                    acc[e][0] += h4.x * w01[0].x; acc[e][1] += h4.x * w01[0].y;
                    acc[e][0] += h4.y * w01[1].x; acc[e][1] += h4.y * w01[1].y;
                    acc[e][0] += h4.z * w01[2].x; acc[e][1] += h4.z * w01[2].y;
                    acc[e][0] += h4.w * w01[3].x; acc[e][1] += h4.w * w01[3].y;
                }
            }
#pragma unroll
            for (int e = 0; e < 8; e++) {
                int ee = eh * 8 + e;
                float2 mv;
                mv.x = silu_f(acc[e][0] + b2_s[j0]);
                mv.y = silu_f(acc[e][1] + b2_s[j0 + 1]);
                *(float2*)&m_s[ee * H + j0] = mv;
            }
        }
        __syncthreads();

        // Phase C: w = silu(m@C1 + cb1) @ C2
        {
            float acc[8][2];
#pragma unroll
            for (int e = 0; e < 8; e++) { acc[e][0] = 0.f; acc[e][1] = 0.f; }
            for (int kk = 0; kk < 128; kk += 4) {
                float2 w01[4];
#pragma unroll
                for (int i = 0; i < 4; i++) w01[i] = *(const float2*)&c1_s[(kk + i) * H + j0];
#pragma unroll
                for (int e = 0; e < 8; e++) {
                    float4 h4 = *(const float4*)&m_s[(eh * 8 + e) * H + kk];
                    acc[e][0] += h4.x * w01[0].x; acc[e][1] += h4.x * w01[0].y;
                    acc[e][0] += h4.y * w01[1].x; acc[e][1] += h4.y * w01[1].y;
                    acc[e][0] += h4.z * w01[2].x; acc[e][1] += h4.z * w01[2].y;
                    acc[e][0] += h4.w * w01[3].x; acc[e][1] += h4.w * w01[3].y;
                }
            }
            float part[8];
#pragma unroll
            for (int e = 0; e < 8; e++) {
                part[e] = silu_f(acc[e][0] + cb1_s[j0]) * c2_s[j0]
                        + silu_f(acc[e][1] + cb1_s[j0 + 1]) * c2_s[j0 + 1];
            }
#pragma unroll
            for (int off = 16; off > 0; off >>= 1) {
#pragma unroll
                for (int e = 0; e < 8; e++)
                    part[e] += __shfl_xor_sync(0xffffffffu, part[e], off);
            }
            if ((t & 31) == 0) {
                int wsel = (t >> 5) & 1;
#pragma unroll
                for (int e = 0; e < 8; e++) wred[(eh * 8 + e) * 2 + wsel] = part[e];
            }
        }
        __syncthreads();
        if (t < 64) wsum_s[t] = wred[t * 2] + wred[t * 2 + 1];
        __syncthreads();

        // Phase D: scatter
#pragma unroll
        for (int rep = 0; rep < 16; rep++) {
            int idx = t + rep * 512;
            int e = idx >> 7, j = idx & 127;
            if (e0 + e < N_EDGES) atomicAdd(&g_agg[row_s[e] * H + j], m_s[e * H + j]);
        }
        if (t < 192) {
            int e = t / 3, k = t % 3;
            if (e0 + e < N_EDGES)
                atomicAdd(&g_posdelta[row_s[e] * 3 + k], rel_s[e * 3 + k] * wsum_s[e]);
        }
        __syncthreads();
    }
}

// ---------------- pos update ----------------
__global__ void k_pos() {
    const int idx = blockIdx.x * blockDim.x + threadIdx.x;
    if (idx >= N_NODES * 3) return;
    const int i = idx / 3;
    float d = fmaxf(g_deg[i], 1.0f);
    g_pos[idx] += g_posdelta[idx] / d;
}

// ---------------- node update stage 1: U = silu([h|agg] @ n_w1 + b1) ----------------
__global__ __launch_bounds__(512, 1) void k_node1(const float* __restrict__ w,
                                                  const float* __restrict__ b) {
    extern __shared__ float sm[];
    float* w_s = sm;              // [256][128]
    float* a_s = sm + 32768;      // [64][256]
    const int t = threadIdx.x;
    const int n0 = blockIdx.x * 64;
    for (int i = t; i < 32768; i += 512) w_s[i] = w[i];
    for (int i = t; i < 16384; i += 512) {
        int n = i >> 8, k = i & 255;
        int gi = n0 + n;
        float v = 0.f;
        if (gi < N_NODES) v = (k < 128) ? g_h[gi * H + k] : g_agg[gi * H + (k - 128)];
        a_s[i] = v;
    }
    __syncthreads();
    const int jp = t & 63, j0 = jp * 2, eh = t >> 6;
    float acc[8][2];
#pragma unroll
    for (int e = 0; e < 8; e++) { acc[e][0] = 0.f; acc[e][1] = 0.f; }
    for (int kk = 0; kk < 256; kk += 4) {
        float2 w01[4];
#pragma unroll
        for (int i = 0; i < 4; i++) w01[i] = *(const float2*)&w_s[(kk + i) * H + j0];
#pragma unroll
        for (int e = 0; e < 8; e++) {
            float4 a = *(const float4*)&a_s[(eh * 8 + e) * 256 + kk];
            acc[e][0] += a.x * w01[0].x; acc[e][1] += a.x * w01[0].y;
            acc[e][0] += a.y * w01[1].x; acc[e][1] += a.y * w01[1].y;
            acc[e][0] += a.z * w01[2].x; acc[e][1] += a.z * w01[2].y;
            acc[e][0] += a.w * w01[3].x; acc[e][1] += a.w * w01[3].y;
        }
    }
    float b0 = b[j0], b1v = b[j0 + 1];
#pragma unroll
    for (int e = 0; e < 8; e++) {
        int gi = n0 + eh * 8 + e;
        if (gi < N_NODES) {
            float2 u;
            u.x = silu_f(acc[e][0] + b0);
            u.y = silu_f(acc[e][1] + b1v);
            *(float2*)&g_U[gi * H + j0] = u;
        }
    }
}

// ---------------- node update stage 2: h += U @ n_w2 + b2 ----------------
__global__ __launch_bounds__(512, 1) void k_node2(const float* __restrict__ w,
                                                  const float* __restrict__ b) {
    extern __shared__ float sm[];
    float* w_s = sm;              // [128][128]
    float* a_s = sm + 16384;      // [64][128]
    const int t = threadIdx.x;
    const int n0 = blockIdx.x * 64;
    for (int i = t; i < 16384; i += 512) w_s[i] = w[i];
    for (int i = t; i < 8192; i += 512) {
        int n = i >> 7, k = i & 127;
        int gi = n0 + n;
        a_s[i] = (gi < N_NODES) ? g_U[gi * H + k] : 0.f;
    }
    __syncthreads();
    const int jp = t & 63, j0 = jp * 2, eh = t >> 6;
    float acc[8][2];
#pragma unroll
    for (int e = 0; e < 8; e++) { acc[e][0] = 0.f; acc[e][1] = 0.f; }
    for (int kk = 0; kk < 128; kk += 4) {
        float2 w01[4];
#pragma unroll
        for (int i = 0; i < 4; i++) w01[i] = *(const float2*)&w_s[(kk + i) * H + j0];
#pragma unroll
        for (int e = 0; e < 8; e++) {
            float4 a = *(const float4*)&a_s[(eh * 8 + e) * H + kk];
            acc[e][0] += a.x * w01[0].x; acc[e][1] += a.x * w01[0].y;
            acc[e][0] += a.y * w01[1].x; acc[e][1] += a.y * w01[1].y;
            acc[e][0] += a.z * w01[2].x; acc[e][1] += a.z * w01[2].y;
            acc[e][0] += a.w * w01[3].x; acc[e][1] += a.w * w01[3].y;
        }
    }
    float b0 = b[j0], b1v = b[j0 + 1];
#pragma unroll
    for (int e = 0; e < 8; e++) {
        int gi = n0 + eh * 8 + e;
        if (gi < N_NODES) {
            float2 hv = *(float2*)&g_h[gi * H + j0];
            hv.x += acc[e][0] + b0;
            hv.y += acc[e][1] + b1v;
            *(float2*)&g_h[gi * H + j0] = hv;
        }
    }
}

// ---------------- pooling ----------------
__global__ void k_pool() {
    const int g = blockIdx.x, j = threadIdx.x;
    float s = 0.f;
    for (int n = 0; n < NPG; n++) s += g_h[(g * NPG + n) * H + j];
    g_gfeat[g * 256 + j] = s;
    g_gfeat[g * 256 + 128 + j] = s * (1.f / (float)NPG);
}

// ---------------- readout head ----------------
__global__ void k_head(const float* __restrict__ h1_w, const float* __restrict__ h1_b,
                       const float* __restrict__ h2_w, const float* __restrict__ h2_b,
                       const float* __restrict__ h3_w, const float* __restrict__ h3_b,
                       float* __restrict__ out) {
    __shared__ float gf[256], z1[128], z2[64];
    const int g = blockIdx.x, t = threadIdx.x;
    gf[t] = g_gfeat[g * 256 + t];
    gf[128 + t] = g_gfeat[g * 256 + 128 + t];
    __syncthreads();
    float a = h1_b[t];
    for (int k = 0; k < 256; k++) a += gf[k] * h1_w[k * 128 + t];
    z1[t] = fmaxf(a, 0.f);
    __syncthreads();
    if (t < 64) {
        float a2 = h2_b[t];
        for (int k = 0; k < 128; k++) a2 += z1[k] * h2_w[k * 64 + t];
        z2[t] = fmaxf(a2, 0.f);
    }
    __syncthreads();
    if (t == 0) {
        float a3 = h3_b[0];
        for (int k = 0; k < 64; k++) a3 += z2[k] * h3_w[k];
        out[g] = a3;
    }
}

// ---------------- launch ----------------
extern "C" void kernel_launch(void* const* d_in, const int* in_sizes, int n_in,
                              void* d_out, int out_size) {
    const float* x     = (const float*)d_in[0];
    const float* pos   = (const float*)d_in[1];
    const int*   ei    = (const int*)d_in[2];
    const float* eattr = (const float*)d_in[3];
    // d_in[4]=batch, d_in[5]=is_protein: derivable from node index, unused
    const float* Wp    = (const float*)d_in[6];
    const float* bp    = (const float*)d_in[7];
    const float* Wl    = (const float*)d_in[8];
    const float* bl    = (const float*)d_in[9];
    const float* gamma = (const float*)d_in[10];
    const float* beta  = (const float*)d_in[11];
    const float* e_w1  = (const float*)d_in[12];
    const float* e_b1  = (const float*)d_in[13];
    const float* e_w2  = (const float*)d_in[14];
    const float* e_b2  = (const float*)d_in[15];
    const float* c_w1  = (const float*)d_in[16];
    const float* c_b1  = (const float*)d_in[17];
    const float* c_w2  = (const float*)d_in[18];
    const float* n_w1  = (const float*)d_in[19];
    const float* n_b1  = (const float*)d_in[20];
    const float* n_w2  = (const float*)d_in[21];
    const float* n_b2  = (const float*)d_in[22];
    const float* h1_w  = (const float*)d_in[23];
    const float* h1_b  = (const float*)d_in[24];
    const float* h2_w  = (const float*)d_in[25];
    const float* h2_b  = (const float*)d_in[26];
    const float* h3_w  = (const float*)d_in[27];
    const float* h3_b  = (const float*)d_in[28];
    float* out = (float*)d_out;

    const int PROJ_SMEM = (32768 + 8192) * 4;
    const int EDGE_SMEM = 204160;
    const int N1_SMEM = (32768 + 16384) * 4;
    const int N2_SMEM = (16384 + 8192) * 4;
    cudaFuncSetAttribute(k_proj,  cudaFuncAttributeMaxDynamicSharedMemorySize, PROJ_SMEM);
    cudaFuncSetAttribute(k_edge,  cudaFuncAttributeMaxDynamicSharedMemorySize, EDGE_SMEM);
    cudaFuncSetAttribute(k_node1, cudaFuncAttributeMaxDynamicSharedMemorySize, N1_SMEM);
    cudaFuncSetAttribute(k_node2, cudaFuncAttributeMaxDynamicSharedMemorySize, N2_SMEM);

    const int nblocks64 = (N_NODES + 63) / 64;   // 782

    k_embed<<<N_NODES, 128>>>(x, pos, Wp, bp, Wl, bl);
    k_bnstats<<<256, 128>>>();
    k_bnapply<<<(N_NODES * H + 511) / 512, 512>>>(gamma, beta);
    k_deg<<<(N_EDGES + 511) / 512, 512>>>(ei);

    for (int l = 0; l < NLAYERS; l++) {
        k_proj<<<nblocks64, 512, PROJ_SMEM>>>(e_w1 + l * 261 * H, e_b1 + l * H);
        k_edge<<<148, 512, EDGE_SMEM>>>(ei, eattr,
                                        e_w2 + l * H * H, e_b2 + l * H,
                                        c_w1 + l * H * H, c_b1 + l * H,
                                        c_w2 + l * H, e_w1 + l * 261 * H);
        k_pos<<<(N_NODES * 3 + 511) / 512, 512>>>();
        k_node1<<<nblocks64, 512, N1_SMEM>>>(n_w1 + l * 256 * H, n_b1 + l * H);
        k_node2<<<nblocks64, 512, N2_SMEM>>>(n_w2 + l * H * H, n_b2 + l * H);
    }

    k_pool<<<G_GRAPHS, 128>>>();
    k_head<<<G_GRAPHS, 128>>>(h1_w, h1_b, h2_w, h2_b, h3_w, h3_b, out);
}

// round 2
// speedup vs baseline: 1.1146x; 1.1146x over previous
#include <cuda_runtime.h>
#include <cuda_bf16.h>

#define N_NODES 50000
#define N_EDGES 500000
#define H 128
#define G_GRAPHS 100
#define NPG 500
#define NPROT 400
#define PN 35
#define LN 11
#define NLAYERS 4
#define EPS 1e-5f
#define NE_TILE 64
#define TP 66   // transposed smem row pad (floats)

// ---------------- scratch ----------------
__device__ float g_h[N_NODES * H];
__device__ float g_P1[N_NODES * H];
__device__ float g_P2[N_NODES * H];
__device__ float g_agg[N_NODES * H];
__device__ float g_U[N_NODES * H];
__device__ float g_pos[N_NODES * 3];
__device__ float g_posdelta[N_NODES * 3];
__device__ float g_deg[N_NODES];
__device__ float g_bnstats[2 * H];
__device__ float g_gfeat[G_GRAPHS * 2 * H];

__device__ __forceinline__ float silu_f(float x) {
    return x / (1.f + __expf(-x));
}

// ---- packed f32x2 helpers (FFMA2 path) ----
__device__ __forceinline__ unsigned long long fma2(unsigned long long a,
                                                   unsigned long long b,
                                                   unsigned long long c) {
    unsigned long long d;
    asm("fma.rn.f32x2 %0, %1, %2, %3;" : "=l"(d) : "l"(a), "l"(b), "l"(c));
    return d;
}
__device__ __forceinline__ unsigned long long dup2(float x) {
    unsigned long long d;
    unsigned int xi = __float_as_uint(x);
    asm("mov.b64 %0, {%1, %1};" : "=l"(d) : "r"(xi));
    return d;
}
__device__ __forceinline__ float2 unpack2(unsigned long long v) {
    unsigned int lo, hi;
    asm("mov.b64 {%0, %1}, %2;" : "=r"(lo), "=r"(hi) : "l"(v));
    float2 r;
    r.x = __uint_as_float(lo);
    r.y = __uint_as_float(hi);
    return r;
}

// ---------------- embed ----------------
__global__ void k_embed(const float* __restrict__ x, const float* __restrict__ pos_in,
                        const float* __restrict__ Wp, const float* __restrict__ bp,
                        const float* __restrict__ Wl, const float* __restrict__ bl) {
    __shared__ float xs[PN];
    const int i = blockIdx.x;
    const int t = threadIdx.x;
    if (t < PN) xs[t] = x[i * PN + t];
    if (t == 0) g_deg[i] = 0.f;
    if (t < 3) g_pos[i * 3 + t] = pos_in[i * 3 + t];
    if (i == 0 && t < H) { g_bnstats[t] = 0.f; g_bnstats[H + t] = 0.f; }
    __syncthreads();
    const bool isp = (i % NPG) < NPROT;
    const float* W = isp ? Wp : Wl;
    const float* b = isp ? bp : bl;
    const int nk = isp ? PN : LN;
    float acc = b[t];
    for (int k = 0; k < nk; k++) acc += xs[k] * W[k * H + t];
    g_h[i * H + t] = acc;
}

// ---------------- batchnorm ----------------
__global__ void k_bnstats() {
    const int j = threadIdx.x;
    float s = 0.f, s2 = 0.f;
    for (int i = blockIdx.x; i < N_NODES; i += gridDim.x) {
        float v = g_h[i * H + j];
        s += v; s2 += v * v;
    }
    atomicAdd(&g_bnstats[j], s);
    atomicAdd(&g_bnstats[H + j], s2);
}

__global__ void k_bnapply(const float* __restrict__ gamma, const float* __restrict__ beta) {
    const int idx = blockIdx.x * blockDim.x + threadIdx.x;
    if (idx >= N_NODES * H) return;
    const int j = idx & (H - 1);
    const float inv_n = 1.f / (float)N_NODES;
    float mu = g_bnstats[j] * inv_n;
    float var = g_bnstats[H + j] * inv_n - mu * mu;
    g_h[idx] = (g_h[idx] - mu) * rsqrtf(var + EPS) * gamma[j] + beta[j];
}

// ---------------- degree ----------------
__global__ void k_deg(const int* __restrict__ ei) {
    const int e = blockIdx.x * blockDim.x + threadIdx.x;
    if (e < N_EDGES) atomicAdd(&g_deg[ei[e]], 1.0f);
}

// ---------------- per-layer node projection (FFMA2) ----------------
// P1 = h@W1a + b1, P2 = h@W1b ; also zero agg/posdelta
__global__ __launch_bounds__(512, 1) void k_proj(const float* __restrict__ w,
                                                 const float* __restrict__ b1) {
    extern __shared__ float sm[];
    float* w_s = sm;            // [128][256]  jj<128 -> W1a col, jj>=128 -> W1b col
    float* a_t = sm + 32768;    // [128 k][TP] transposed activations (64 nodes)
    const int t = threadIdx.x;
    const int n0 = blockIdx.x * 64;

    for (int i = t; i < 32768; i += 512) {
        int k = i >> 8, jj = i & 255;
        int srcrow = (jj < 128) ? k : (128 + k);
        w_s[i] = w[srcrow * H + (jj & 127)];
    }
    for (int i = t; i < 8192; i += 512) {
        int n = i >> 7, k = i & 127;
        int gi = n0 + n;
        a_t[k * TP + n] = (gi < N_NODES) ? g_h[gi * H + k] : 0.f;
    }
    for (int i = t; i < 64 * H; i += 512) {
        int gi = n0 + (i >> 7);
        if (gi < N_NODES) g_agg[gi * H + (i & 127)] = 0.f;
    }
    if (t < 192) {
        int gi = n0 + t / 3;
        if (gi < N_NODES) g_posdelta[gi * 3 + t % 3] = 0.f;
    }
    __syncthreads();

    const int j0 = (t & 127) * 2;   // 0..254, pair stays within one half
    const int eh = t >> 7;          // 0..3 -> 16 nodes each
    const int nb = eh * 16;
    unsigned long long acc0[8], acc1[8];
#pragma unroll
    for (int p = 0; p < 8; p++) { acc0[p] = 0ull; acc1[p] = 0ull; }

#pragma unroll 2
    for (int k = 0; k < 128; k++) {
        float2 wp = *(const float2*)&w_s[k * 256 + j0];
        unsigned long long bd0 = dup2(wp.x), bd1 = dup2(wp.y);
        const float* ar = &a_t[k * TP + nb];
#pragma unroll
        for (int p = 0; p < 8; p++) {
            unsigned long long av = *(const unsigned long long*)&ar[2 * p];
            acc0[p] = fma2(av, bd0, acc0[p]);
            acc1[p] = fma2(av, bd1, acc1[p]);
        }
    }

    const int half = j0 >> 7;
    const int j = j0 & 127;
    float* outp = half ? g_P2 : g_P1;
    const float bb0 = half ? 0.f : b1[j];
    const float bb1 = half ? 0.f : b1[j + 1];
#pragma unroll
    for (int p = 0; p < 8; p++) {
        float2 a0 = unpack2(acc0[p]);   // col j : nodes (2p, 2p+1)
        float2 a1 = unpack2(acc1[p]);   // col j+1
        int n0g = n0 + nb + 2 * p;
        if (n0g < N_NODES) {
            float2 v = make_float2(a0.x + bb0, a1.x + bb1);
            *(float2*)&outp[n0g * H + j] = v;
        }
        if (n0g + 1 < N_NODES) {
            float2 v = make_float2(a0.y + bb0, a1.y + bb1);
            *(float2*)&outp[(n0g + 1) * H + j] = v;
        }
    }
}

// ---------------- fused edge kernel (FFMA2 GEMMs) ----------------
__global__ __launch_bounds__(512, 1) void k_edge(
    const int* __restrict__ ei, const float* __restrict__ eattr,
    const float* __restrict__ w2, const float* __restrict__ b2,
    const float* __restrict__ cw1, const float* __restrict__ cb1,
    const float* __restrict__ cw2, const float* __restrict__ ew1) {
    extern __shared__ float sm[];
    float* w2_s  = sm;                // 16384 [k][j]
    float* c1_s  = w2_s + 16384;      // 16384
    float* b2_s  = c1_s + 16384;      // 128
    float* cb1_s = b2_s + 128;        // 128
    float* c2_s  = cb1_s + 128;       // 128
    float* wd2_s = c2_s + 128;        // 128
    float* wea_s = wd2_s + 128;       // 512
    float* hid_t = wea_s + 512;       // [128 k][TP] transposed, 8448
    float* m_t   = hid_t + 128 * TP;  // 8448
    float* d2_s  = m_t + 128 * TP;    // 64
    float* rel_s = d2_s + 64;         // 192
    float* ea_s  = rel_s + 192;       // 256
    float* wsum_s = ea_s + 256;       // 64
    float* wred  = wsum_s + 64;       // 128
    int* row_s = (int*)(wred + 128);  // 64
    int* col_s = row_s + 64;          // 64

    const int t = threadIdx.x;
    for (int i = t; i < 16384; i += 512) { w2_s[i] = w2[i]; c1_s[i] = cw1[i]; }
    if (t < 128) {
        b2_s[t] = b2[t]; cb1_s[t] = cb1[t]; c2_s[t] = cw2[t];
        wd2_s[t] = ew1[256 * H + t];
    }
    if (t < 512) wea_s[t] = ew1[257 * H + t];
    __syncthreads();

    const int j0 = (t & 63) * 2;
    const int eh = t >> 6;      // 0..7, 8 edges each
    const int ebase = eh * 8;
    const int ntiles = (N_EDGES + NE_TILE - 1) / NE_TILE;

    for (int tile = blockIdx.x; tile < ntiles; tile += gridDim.x) {
        const int e0 = tile * NE_TILE;
        if (t < NE_TILE) {
            int e = e0 + t;
            int r = 0, c = 0;
            float4 a = make_float4(0.f, 0.f, 0.f, 0.f);
            if (e < N_EDGES) {
                r = ei[e]; c = ei[N_EDGES + e];
                a = *(const float4*)&eattr[e * 4];
            }
            row_s[t] = r; col_s[t] = c;
            float rx = g_pos[r * 3 + 0] - g_pos[c * 3 + 0];
            float ry = g_pos[r * 3 + 1] - g_pos[c * 3 + 1];
            float rz = g_pos[r * 3 + 2] - g_pos[c * 3 + 2];
            rel_s[t * 3 + 0] = rx; rel_s[t * 3 + 1] = ry; rel_s[t * 3 + 2] = rz;
            d2_s[t] = rx * rx + ry * ry + rz * rz;
            ea_s[t * 4 + 0] = a.x; ea_s[t * 4 + 1] = a.y;
            ea_s[t * 4 + 2] = a.z; ea_s[t * 4 + 3] = a.w;
        }
        __syncthreads();

        // Phase A: hidden (transposed store)
#pragma unroll
        for (int rep = 0; rep < 16; rep++) {
            int idx = t + rep * 512;
            int e = idx >> 7, j = idx & 127;
            int r = row_s[e], c = col_s[e];
            float v = g_P1[r * H + j] + g_P2[c * H + j] + d2_s[e] * wd2_s[j];
#pragma unroll
            for (int a2 = 0; a2 < 4; a2++) v += ea_s[e * 4 + a2] * wea_s[a2 * H + j];
            hid_t[j * TP + e] = silu_f(v);
        }
        __syncthreads();

        // Phase B: m = silu(hid @ W2 + b2)  (FFMA2, edge-pair packed)
        {
            unsigned long long acc0[4], acc1[4];
#pragma unroll
            for (int p = 0; p < 4; p++) { acc0[p] = 0ull; acc1[p] = 0ull; }
#pragma unroll 4
            for (int k = 0; k < 128; k++) {
                float2 wp = *(const float2*)&w2_s[k * H + j0];
                unsigned long long bd0 = dup2(wp.x), bd1 = dup2(wp.y);
                const float* hr = &hid_t[k * TP + ebase];
#pragma unroll
                for (int p = 0; p < 4; p++) {
                    unsigned long long av = *(const unsigned long long*)&hr[2 * p];
                    acc0[p] = fma2(av, bd0, acc0[p]);
                    acc1[p] = fma2(av, bd1, acc1[p]);
                }
            }
            float b0 = b2_s[j0], b1v = b2_s[j0 + 1];
#pragma unroll
            for (int p = 0; p < 4; p++) {
                float2 a0 = unpack2(acc0[p]);
                float2 a1 = unpack2(acc1[p]);
                float2 o0 = make_float2(silu_f(a0.x + b0), silu_f(a0.y + b0));
                float2 o1 = make_float2(silu_f(a1.x + b1v), silu_f(a1.y + b1v));
                *(float2*)&m_t[j0 * TP + ebase + 2 * p] = o0;
                *(float2*)&m_t[(j0 + 1) * TP + ebase + 2 * p] = o1;
            }
        }
        __syncthreads();

        // Phase C: w = silu(m@C1 + cb1) @ C2  (FFMA2)
        {
            unsigned long long acc0[4], acc1[4];
#pragma unroll
            for (int p = 0; p < 4; p++) { acc0[p] = 0ull; acc1[p] = 0ull; }
#pragma unroll 4
            for (int k = 0; k < 128; k++) {
                float2 wp = *(const float2*)&c1_s[k * H + j0];
                unsigned long long bd0 = dup2(wp.x), bd1 = dup2(wp.y);
                const float* mr = &m_t[k * TP + ebase];
#pragma unroll
                for (int p = 0; p < 4; p++) {
                    unsigned long long av = *(const unsigned long long*)&mr[2 * p];
                    acc0[p] = fma2(av, bd0, acc0[p]);
                    acc1[p] = fma2(av, bd1, acc1[p]);
                }
            }
            float cb0 = cb1_s[j0], cb1v = cb1_s[j0 + 1];
            float c20 = c2_s[j0], c21 = c2_s[j0 + 1];
            float part[8];
#pragma unroll
            for (int p = 0; p < 4; p++) {
                float2 a0 = unpack2(acc0[p]);
                float2 a1 = unpack2(acc1[p]);
                part[2 * p]     = silu_f(a0.x + cb0) * c20 + silu_f(a1.x + cb1v) * c21;
                part[2 * p + 1] = silu_f(a0.y + cb0) * c20 + silu_f(a1.y + cb1v) * c21;
            }
#pragma unroll
            for (int off = 16; off > 0; off >>= 1) {
#pragma unroll
                for (int e = 0; e < 8; e++)
                    part[e] += __shfl_xor_sync(0xffffffffu, part[e], off);
            }
            if ((t & 31) == 0) {
                int wsel = (t >> 5) & 1;
#pragma unroll
                for (int e = 0; e < 8; e++) wred[(ebase + e) * 2 + wsel] = part[e];
            }
        }
        __syncthreads();
        if (t < 64) wsum_s[t] = wred[t * 2] + wred[t * 2 + 1];
        __syncthreads();

        // Phase D: scatter
#pragma unroll
        for (int rep = 0; rep < 16; rep++) {
            int idx = t + rep * 512;
            int e = idx >> 7, j = idx & 127;
            if (e0 + e < N_EDGES) atomicAdd(&g_agg[row_s[e] * H + j], m_t[j * TP + e]);
        }
        if (t < 192) {
            int e = t / 3, k = t % 3;
            if (e0 + e < N_EDGES)
                atomicAdd(&g_posdelta[row_s[e] * 3 + k], rel_s[e * 3 + k] * wsum_s[e]);
        }
        __syncthreads();
    }
}

// ---------------- pos update ----------------
__global__ void k_pos() {
    const int idx = blockIdx.x * blockDim.x + threadIdx.x;
    if (idx >= N_NODES * 3) return;
    const int i = idx / 3;
    float d = fmaxf(g_deg[i], 1.0f);
    g_pos[idx] += g_posdelta[idx] / d;
}

// ---------------- node stage 1: U = silu([h|agg] @ n_w1 + b1)  (FFMA2) ----------------
__global__ __launch_bounds__(512, 1) void k_node1(const float* __restrict__ w,
                                                  const float* __restrict__ b) {
    extern __shared__ float sm[];
    float* w_s = sm;              // [256][128]
    float* a_t = sm + 32768;      // [256 k][TP]
    const int t = threadIdx.x;
    const int n0 = blockIdx.x * 64;
    for (int i = t; i < 32768; i += 512) w_s[i] = w[i];
    for (int i = t; i < 16384; i += 512) {
        int n = i >> 8, k = i & 255;
        int gi = n0 + n;
        float v = 0.f;
        if (gi < N_NODES) v = (k < 128) ? g_h[gi * H + k] : g_agg[gi * H + (k - 128)];
        a_t[k * TP + n] = v;
    }
    __syncthreads();

    const int j0 = (t & 63) * 2;
    const int eh = t >> 6;
    const int nb = eh * 8;
    unsigned long long acc0[4], acc1[4];
#pragma unroll
    for (int p = 0; p < 4; p++) { acc0[p] = 0ull; acc1[p] = 0ull; }
#pragma unroll 4
    for (int k = 0; k < 256; k++) {
        float2 wp = *(const float2*)&w_s[k * H + j0];
        unsigned long long bd0 = dup2(wp.x), bd1 = dup2(wp.y);
        const float* ar = &a_t[k * TP + nb];
#pragma unroll
        for (int p = 0; p < 4; p++) {
            unsigned long long av = *(const unsigned long long*)&ar[2 * p];
            acc0[p] = fma2(av, bd0, acc0[p]);
            acc1[p] = fma2(av, bd1, acc1[p]);
        }
    }
    float b0 = b[j0], b1v = b[j0 + 1];
#pragma unroll
    for (int p = 0; p < 4; p++) {
        float2 a0 = unpack2(acc0[p]);
        float2 a1 = unpack2(acc1[p]);
        int n0g = n0 + nb + 2 * p;
        if (n0g < N_NODES) {
            float2 u = make_float2(silu_f(a0.x + b0), silu_f(a1.x + b1v));
            *(float2*)&g_U[n0g * H + j0] = u;
        }
        if (n0g + 1 < N_NODES) {
            float2 u = make_float2(silu_f(a0.y + b0), silu_f(a1.y + b1v));
            *(float2*)&g_U[(n0g + 1) * H + j0] = u;
        }
    }
}

// ---------------- node stage 2: h += U @ n_w2 + b2  (FFMA2) ----------------
__global__ __launch_bounds__(512, 1) void k_node2(const float* __restrict__ w,
                                                  const float* __restrict__ b) {
    extern __shared__ float sm[];
    float* w_s = sm;              // [128][128]
    float* a_t = sm + 16384;      // [128 k][TP]
    const int t = threadIdx.x;
    const int n0 = blockIdx.x * 64;
    for (int i = t; i < 16384; i += 512) w_s[i] = w[i];
    for (int i = t; i < 8192; i += 512) {
        int n = i >> 7, k = i & 127;
        int gi = n0 + n;
        a_t[k * TP + n] = (gi < N_NODES) ? g_U[gi * H + k] : 0.f;
    }
    __syncthreads();

    const int j0 = (t & 63) * 2;
    const int eh = t >> 6;
    const int nb = eh * 8;
    unsigned long long acc0[4], acc1[4];
#pragma unroll
    for (int p = 0; p < 4; p++) { acc0[p] = 0ull; acc1[p] = 0ull; }
#pragma unroll 4
    for (int k = 0; k < 128; k++) {
        float2 wp = *(const float2*)&w_s[k * H + j0];
        unsigned long long bd0 = dup2(wp.x), bd1 = dup2(wp.y);
        const float* ar = &a_t[k * TP + nb];
#pragma unroll
        for (int p = 0; p < 4; p++) {
            unsigned long long av = *(const unsigned long long*)&ar[2 * p];
            acc0[p] = fma2(av, bd0, acc0[p]);
            acc1[p] = fma2(av, bd1, acc1[p]);
        }
    }
    float b0 = b[j0], b1v = b[j0 + 1];
#pragma unroll
    for (int p = 0; p < 4; p++) {
        float2 a0 = unpack2(acc0[p]);
        float2 a1 = unpack2(acc1[p]);
        int n0g = n0 + nb + 2 * p;
        if (n0g < N_NODES) {
            float2 hv = *(float2*)&g_h[n0g * H + j0];
            hv.x += a0.x + b0; hv.y += a1.x + b1v;
            *(float2*)&g_h[n0g * H + j0] = hv;
        }
        if (n0g + 1 < N_NODES) {
            float2 hv = *(float2*)&g_h[(n0g + 1) * H + j0];
            hv.x += a0.y + b0; hv.y += a1.y + b1v;
            *(float2*)&g_h[(n0g + 1) * H + j0] = hv;
        }
    }
}

// ---------------- pooling ----------------
__global__ void k_pool() {
    const int g = blockIdx.x, j = threadIdx.x;
    float s = 0.f;
    for (int n = 0; n < NPG; n++) s += g_h[(g * NPG + n) * H + j];
    g_gfeat[g * 256 + j] = s;
    g_gfeat[g * 256 + 128 + j] = s * (1.f / (float)NPG);
}

// ---------------- readout head ----------------
__global__ void k_head(const float* __restrict__ h1_w, const float* __restrict__ h1_b,
                       const float* __restrict__ h2_w, const float* __restrict__ h2_b,
                       const float* __restrict__ h3_w, const float* __restrict__ h3_b,
                       float* __restrict__ out) {
    __shared__ float gf[256], z1[128], z2[64];
    const int g = blockIdx.x, t = threadIdx.x;
    gf[t] = g_gfeat[g * 256 + t];
    gf[128 + t] = g_gfeat[g * 256 + 128 + t];
    __syncthreads();
    float a = h1_b[t];
    for (int k = 0; k < 256; k++) a += gf[k] * h1_w[k * 128 + t];
    z1[t] = fmaxf(a, 0.f);
    __syncthreads();
    if (t < 64) {
        float a2 = h2_b[t];
        for (int k = 0; k < 128; k++) a2 += z1[k] * h2_w[k * 64 + t];
        z2[t] = fmaxf(a2, 0.f);
    }
    __syncthreads();
    if (t == 0) {
        float a3 = h3_b[0];
        for (int k = 0; k < 64; k++) a3 += z2[k] * h3_w[k];
        out[g] = a3;
    }
}

// ---------------- launch ----------------
extern "C" void kernel_launch(void* const* d_in, const int* in_sizes, int n_in,
                              void* d_out, int out_size) {
    const float* x     = (const float*)d_in[0];
    const float* pos   = (const float*)d_in[1];
    const int*   ei    = (const int*)d_in[2];
    const float* eattr = (const float*)d_in[3];
    const float* Wp    = (const float*)d_in[6];
    const float* bp    = (const float*)d_in[7];
    const float* Wl    = (const float*)d_in[8];
    const float* bl    = (const float*)d_in[9];
    const float* gamma = (const float*)d_in[10];
    const float* beta  = (const float*)d_in[11];
    const float* e_w1  = (const float*)d_in[12];
    const float* e_b1  = (const float*)d_in[13];
    const float* e_w2  = (const float*)d_in[14];
    const float* e_b2  = (const float*)d_in[15];
    const float* c_w1  = (const float*)d_in[16];
    const float* c_b1  = (const float*)d_in[17];
    const float* c_w2  = (const float*)d_in[18];
    const float* n_w1  = (const float*)d_in[19];
    const float* n_b1  = (const float*)d_in[20];
    const float* n_w2  = (const float*)d_in[21];
    const float* n_b2  = (const float*)d_in[22];
    const float* h1_w  = (const float*)d_in[23];
    const float* h1_b  = (const float*)d_in[24];
    const float* h2_w  = (const float*)d_in[25];
    const float* h2_b  = (const float*)d_in[26];
    const float* h3_w  = (const float*)d_in[27];
    const float* h3_b  = (const float*)d_in[28];
    float* out = (float*)d_out;

    const int PROJ_SMEM = (32768 + 128 * TP) * 4;
    const int EDGE_SMEM = (16384 * 2 + 128 * 5 + 512 + 2 * 128 * TP
                           + 64 + 192 + 256 + 64 + 128 + 128) * 4;
    const int N1_SMEM = (32768 + 256 * TP) * 4;
    const int N2_SMEM = (16384 + 128 * TP) * 4;
    cudaFuncSetAttribute(k_proj,  cudaFuncAttributeMaxDynamicSharedMemorySize, PROJ_SMEM);
    cudaFuncSetAttribute(k_edge,  cudaFuncAttributeMaxDynamicSharedMemorySize, EDGE_SMEM);
    cudaFuncSetAttribute(k_node1, cudaFuncAttributeMaxDynamicSharedMemorySize, N1_SMEM);
    cudaFuncSetAttribute(k_node2, cudaFuncAttributeMaxDynamicSharedMemorySize, N2_SMEM);

    const int nblocks64 = (N_NODES + 63) / 64;   // 782

    k_embed<<<N_NODES, 128>>>(x, pos, Wp, bp, Wl, bl);
    k_bnstats<<<256, 128>>>();
    k_bnapply<<<(N_NODES * H + 511) / 512, 512>>>(gamma, beta);
    k_deg<<<(N_EDGES + 511) / 512, 512>>>(ei);

    for (int l = 0; l < NLAYERS; l++) {
        k_proj<<<nblocks64, 512, PROJ_SMEM>>>(e_w1 + l * 261 * H, e_b1 + l * H);
        k_edge<<<148, 512, EDGE_SMEM>>>(ei, eattr,
                                        e_w2 + l * H * H, e_b2 + l * H,
                                        c_w1 + l * H * H, c_b1 + l * H,
                                        c_w2 + l * H, e_w1 + l * 261 * H);
        k_pos<<<(N_NODES * 3 + 511) / 512, 512>>>();
        k_node1<<<nblocks64, 512, N1_SMEM>>>(n_w1 + l * 256 * H, n_b1 + l * H);
        k_node2<<<nblocks64, 512, N2_SMEM>>>(n_w2 + l * H * H, n_b2 + l * H);
    }

    k_pool<<<G_GRAPHS, 128>>>();
    k_head<<<G_GRAPHS, 128>>>(h1_w, h1_b, h2_w, h2_b, h3_w, h3_b, out);
}